// round 13
// baseline (speedup 1.0000x reference)
#include <cuda_runtime.h>
#include <cuda_bf16.h>
#include <cuda_fp8.h>
#include <cstdint>

#define Bb 8
#define Cc 512
#define Ll 4096
#define Dd 64

#define PSCALE (1.0f / 64.0f)

// ---------------------------------------------------------------------------
// Scratch (device globals)
// ---------------------------------------------------------------------------
__device__ __nv_bfloat16 g_qa[(size_t)Bb * Ll * Dd];    // [B,L,64] q bf16
__device__ __nv_bfloat16 g_kb[(size_t)Bb * Ll * Dd];    // [B,L,64] k bf16
__device__ __nv_bfloat16 g_xT[(size_t)Bb * Ll * Cc];    // [B,L,C] bf16
__device__ __nv_bfloat16 g_wv[(size_t)Cc * Cc];         // [C,C] bf16
__device__ __nv_bfloat16 g_wqk[128 * Cc];               // [128,C] = [Wq;Wk] bf16
__device__ float         g_bqk[128];                    // [bq|bk]
__device__ unsigned char g_v [(size_t)Bb * Cc * Ll];    // [B,C,L] e4m3
__device__ unsigned char g_p [(size_t)Bb * Ll * Ll];    // [B,L,L] e4m3 exp(e)*2^-6
__device__ float g_spart[(size_t)Bb * 8 * Ll];          // [B,ngroup,L] partials
__device__ float g_invs [(size_t)Bb * Ll];              // [B,L] 1/rowsum

// ---------------------------------------------------------------------------
// helpers
// ---------------------------------------------------------------------------
__device__ __forceinline__ uint32_t smem_u32(const void* p) {
    uint32_t a;
    asm("{ .reg .u64 t; cvta.to.shared.u64 t, %1; cvt.u32.u64 %0, t; }"
        : "=r"(a) : "l"(p));
    return a;
}
__device__ __forceinline__ void cp16u(uint32_t s, const void* g) {
    asm volatile("cp.async.cg.shared.global [%0], [%1], 16;" :: "r"(s), "l"(g));
}
__device__ __forceinline__ void ldsm_x4(uint32_t* r, uint32_t addr) {
    asm volatile("ldmatrix.sync.aligned.m8n8.x4.shared.b16 {%0,%1,%2,%3}, [%4];"
                 : "=r"(r[0]), "=r"(r[1]), "=r"(r[2]), "=r"(r[3]) : "r"(addr));
}
__device__ __forceinline__ void mma16816(float* d, const uint32_t* a, const uint32_t* b) {
    asm volatile(
        "mma.sync.aligned.m16n8k16.row.col.f32.bf16.bf16.f32 "
        "{%0,%1,%2,%3}, {%4,%5,%6,%7}, {%8,%9}, {%0,%1,%2,%3};"
        : "+f"(d[0]), "+f"(d[1]), "+f"(d[2]), "+f"(d[3])
        : "r"(a[0]), "r"(a[1]), "r"(a[2]), "r"(a[3]), "r"(b[0]), "r"(b[1]));
}
__device__ __forceinline__ void mma16832f8(float* d, const uint32_t* a,
                                           uint32_t b0, uint32_t b1) {
    asm volatile(
        "mma.sync.aligned.m16n8k32.row.col.f32.e4m3.e4m3.f32 "
        "{%0,%1,%2,%3}, {%4,%5,%6,%7}, {%8,%9}, {%0,%1,%2,%3};"
        : "+f"(d[0]), "+f"(d[1]), "+f"(d[2]), "+f"(d[3])
        : "r"(a[0]), "r"(a[1]), "r"(a[2]), "r"(a[3]), "r"(b0), "r"(b1));
}
__device__ __forceinline__ unsigned short f2_fp8x2(float a, float b) {
    float2 f; f.x = a; f.y = b;
    return (unsigned short)__nv_cvt_float2_to_fp8x2(f, __NV_SATFINITE, __NV_E4M3);
}

static constexpr int STAGE_BYTES = 32768;
static constexpr int SMEM_SZ = 3 * STAGE_BYTES + 1024;
static constexpr int ESMEM_SZ = 4 * 16384 + 1024;

// ---------------------------------------------------------------------------
// bf16 HMMA GEMM: CTA 128x128, 256 thr (4m x 2n), k-tile 64, 3-stage.
// EPI 1: +bias[m], store e4m3
// EPI 4: +bias[n] stacked, split cols -> q / k bf16
// ---------------------------------------------------------------------------
template <int EPI>
__global__ __launch_bounds__(256, 2) void hgemm(
    const __nv_bfloat16* __restrict__ Aall,
    const __nv_bfloat16* __restrict__ Ball,
    unsigned char* __restrict__ Cout,
    void* __restrict__ Cout2,
    int K, int ldC,
    long long sA, long long sB, long long sC,
    const float* __restrict__ bias)
{
    extern __shared__ __align__(1024) char sm[];
    const uint32_t smA = smem_u32(sm);
    const uint32_t smB = smA + 16384;

    const int t = threadIdx.x, lane = t & 31, wid = t >> 5;
    const int bz = blockIdx.z;
    const int m0 = blockIdx.y * 128, n0 = blockIdx.x * 128;
    const int wm = wid & 3, wn = wid >> 2;

    const __nv_bfloat16* A = Aall + (size_t)bz * sA + (size_t)m0 * K;
    const __nv_bfloat16* B = Ball + (size_t)bz * sB + (size_t)n0 * K;

    const int lrow = t >> 1;
    const int lc0  = (t & 1) * 4;
    const int lswz = lrow & 7;
    const __nv_bfloat16* Ar = A + (size_t)lrow * K;
    const __nv_bfloat16* Br = B + (size_t)lrow * K;
    const uint32_t dA0 = smA + lrow * 128;
    const uint32_t dB0 = smB + lrow * 128;

    float acc[2][8][4];
#pragma unroll
    for (int i = 0; i < 2; i++)
#pragma unroll
        for (int j = 0; j < 8; j++)
#pragma unroll
            for (int q = 0; q < 4; q++) acc[i][j][q] = 0.f;

#define LOAD_TILE(stg, k0)                                                   \
    do {                                                                     \
        _Pragma("unroll")                                                    \
        for (int j = 0; j < 4; j++) {                                        \
            int c = lc0 + j;                                                 \
            uint32_t ph = (uint32_t)((c ^ lswz) << 4);                       \
            cp16u(dA0 + (stg) * STAGE_BYTES + ph, Ar + (k0) + c * 8);        \
            cp16u(dB0 + (stg) * STAGE_BYTES + ph, Br + (k0) + c * 8);        \
        }                                                                    \
        asm volatile("cp.async.commit_group;");                              \
    } while (0)

    const int nk = K / 64;
    LOAD_TILE(0, 0);
    if (nk > 1) LOAD_TILE(1, 64);

    const int a_r = lane & 15;
    const int a_ch = lane >> 4;
    const int b_r = ((lane >> 4) << 3) + (lane & 7);
    const int b_ch = (lane >> 3) & 1;

    int buf = 0;
    for (int kt = 0; kt < nk; kt++) {
        if (kt + 1 < nk) asm volatile("cp.async.wait_group 1;");
        else             asm volatile("cp.async.wait_group 0;");
        __syncthreads();

        if (kt + 2 < nk) {
            const int slot = (buf + 2 >= 3) ? buf - 1 : buf + 2;
            LOAD_TILE(slot, (kt + 2) * 64);
        }

        const uint32_t bA = smA + buf * STAGE_BYTES;
        const uint32_t bB = smB + buf * STAGE_BYTES;

        uint32_t af[2][2][4];
        uint32_t bf_[2][4][4];

#define LOAD_FRAGS(pp, s)                                                    \
    do {                                                                     \
        _Pragma("unroll")                                                    \
        for (int mt = 0; mt < 2; mt++) {                                     \
            int r = wm * 32 + mt * 16 + a_r;                                 \
            int c = (s) * 2 + a_ch;                                          \
            ldsm_x4(af[pp][mt], bA + r * 128 + ((c ^ (r & 7)) << 4));        \
        }                                                                    \
        _Pragma("unroll")                                                    \
        for (int ng = 0; ng < 4; ng++) {                                     \
            int r = wn * 64 + ng * 16 + b_r;                                 \
            int c = (s) * 2 + b_ch;                                          \
            ldsm_x4(bf_[pp][ng], bB + r * 128 + ((c ^ (r & 7)) << 4));       \
        }                                                                    \
    } while (0)

        LOAD_FRAGS(0, 0);
#pragma unroll
        for (int s = 0; s < 4; s++) {
            if (s < 3) LOAD_FRAGS((s + 1) & 1, s + 1);
#pragma unroll
            for (int mt = 0; mt < 2; mt++)
#pragma unroll
                for (int nt = 0; nt < 8; nt++)
                    mma16816(acc[mt][nt], af[s & 1][mt],
                             &bf_[s & 1][nt >> 1][(nt & 1) * 2]);
        }
#undef LOAD_FRAGS
        buf = (buf + 1 == 3) ? 0 : buf + 1;
    }
#undef LOAD_TILE

    const int cr = lane >> 2;
    const int cc = (lane & 3) * 2;

    if (EPI == 1) {
        unsigned char* C = Cout + (size_t)bz * sC;
#pragma unroll
        for (int mt = 0; mt < 2; mt++) {
            float bv0 = bias[m0 + wm * 32 + mt * 16 + cr];
            float bv1 = bias[m0 + wm * 32 + mt * 16 + cr + 8];
#pragma unroll
            for (int nt = 0; nt < 8; nt++) {
                int col = n0 + wn * 64 + nt * 8 + cc;
#pragma unroll
                for (int h = 0; h < 2; h++) {
                    int row = m0 + wm * 32 + mt * 16 + cr + h * 8;
                    float bv = h ? bv1 : bv0;
                    *(unsigned short*)(C + (size_t)row * ldC + col) =
                        f2_fp8x2(acc[mt][nt][h * 2] + bv, acc[mt][nt][h * 2 + 1] + bv);
                }
            }
        }
    } else {
        __nv_bfloat16* Q  = (__nv_bfloat16*)Cout  + (size_t)bz * Ll * Dd;
        __nv_bfloat16* Kk = (__nv_bfloat16*)Cout2 + (size_t)bz * Ll * Dd;
#pragma unroll
        for (int nt = 0; nt < 8; nt++) {
            int col = wn * 64 + nt * 8 + cc;
            float bv0 = bias[col];
            float bv1 = bias[col + 1];
            __nv_bfloat16* dst = (col < 64) ? Q : Kk;
            int dcol = col & 63;
#pragma unroll
            for (int mt = 0; mt < 2; mt++)
#pragma unroll
                for (int h = 0; h < 2; h++) {
                    int row = m0 + wm * 32 + mt * 16 + cr + h * 8;
                    __nv_bfloat162 o;
                    o.x = __float2bfloat16(acc[mt][nt][h * 2] + bv0);
                    o.y = __float2bfloat16(acc[mt][nt][h * 2 + 1] + bv1);
                    *(__nv_bfloat162*)(dst + (size_t)row * Dd + dcol) = o;
                }
        }
    }
}

// ---------------------------------------------------------------------------
// Energy GEMM (per batch-chunk): p = exp(q @ k^T)*2^-6, K=64.
// A resident; loops 4 consecutive n-tiles; rowsums -> spart [.,8,L].
// Pointers pre-offset by batch chunk; grid z = chunk size.
// ---------------------------------------------------------------------------
__global__ __launch_bounds__(256, 2) void egemm(
    const __nv_bfloat16* __restrict__ Qall,
    const __nv_bfloat16* __restrict__ Kall,
    unsigned char* __restrict__ Pout,
    float* __restrict__ spart)
{
    constexpr int NTPC = 4;
    extern __shared__ __align__(1024) char sm[];
    const uint32_t smA = smem_u32(sm);
    const uint32_t smB = smA + 16384;
    float* s_part = (float*)(sm + 4 * 16384);

    const int t = threadIdx.x, lane = t & 31, wid = t >> 5;
    const int bz = blockIdx.z;
    const int m0 = blockIdx.y * 128;
    const int ng = blockIdx.x;
    const int wm = wid & 3, wn = wid >> 2;

    const __nv_bfloat16* Q  = Qall + (size_t)bz * Ll * Dd + (size_t)m0 * Dd;
    const __nv_bfloat16* Kb = Kall + (size_t)bz * Ll * Dd
                              + (size_t)ng * NTPC * 128 * Dd;

    const int lrow = t >> 1;
    const int lc0  = (t & 1) * 4;
    const int lswz = lrow & 7;
    const __nv_bfloat16* Ar = Q  + (size_t)lrow * Dd;
    const __nv_bfloat16* Br = Kb + (size_t)lrow * Dd;
    const uint32_t dA = smA + lrow * 128;
    const uint32_t dB = smB + lrow * 128;

#pragma unroll
    for (int j = 0; j < 4; j++) {
        int c = lc0 + j;
        uint32_t ph = (uint32_t)((c ^ lswz) << 4);
        cp16u(dA + ph, Ar + c * 8);
        cp16u(dB + ph, Br + c * 8);
    }
    asm volatile("cp.async.commit_group;");
#pragma unroll
    for (int j = 0; j < 4; j++) {
        int c = lc0 + j;
        uint32_t ph = (uint32_t)((c ^ lswz) << 4);
        cp16u(dB + 16384 + ph, Br + 8192 + c * 8);
    }
    asm volatile("cp.async.commit_group;");

    const int a_r = lane & 15;
    const int a_ch = lane >> 4;
    const int b_r = ((lane >> 4) << 3) + (lane & 7);
    const int b_ch = (lane >> 3) & 1;
    const int cr = lane >> 2;
    const int cc = (lane & 3) * 2;

    float rs[2][2] = {{0.f, 0.f}, {0.f, 0.f}};
    unsigned char* P = Pout + (size_t)bz * Ll * Ll;

    for (int it = 0; it < NTPC; it++) {
        asm volatile("cp.async.wait_group 1;");
        __syncthreads();

        if (it + 2 < NTPC) {
            const int stg = (it + 2) % 3;
#pragma unroll
            for (int j = 0; j < 4; j++) {
                int c = lc0 + j;
                uint32_t ph = (uint32_t)((c ^ lswz) << 4);
                cp16u(dB + stg * 16384 + ph, Br + (size_t)(it + 2) * 8192 + c * 8);
            }
        }
        asm volatile("cp.async.commit_group;");

        const uint32_t bB = smB + (it % 3) * 16384;

        float acc[2][8][4];
#pragma unroll
        for (int i = 0; i < 2; i++)
#pragma unroll
            for (int j = 0; j < 8; j++)
#pragma unroll
                for (int q = 0; q < 4; q++) acc[i][j][q] = 0.f;

        uint32_t af[2][2][4];
        uint32_t bf_[2][4][4];

#define E_LOAD_FRAGS(pp, s)                                                  \
    do {                                                                     \
        _Pragma("unroll")                                                    \
        for (int mt = 0; mt < 2; mt++) {                                     \
            int r = wm * 32 + mt * 16 + a_r;                                 \
            int c = (s) * 2 + a_ch;                                          \
            ldsm_x4(af[pp][mt], smA + r * 128 + ((c ^ (r & 7)) << 4));       \
        }                                                                    \
        _Pragma("unroll")                                                    \
        for (int g = 0; g < 4; g++) {                                        \
            int r = wn * 64 + g * 16 + b_r;                                  \
            int c = (s) * 2 + b_ch;                                          \
            ldsm_x4(bf_[pp][g], bB + r * 128 + ((c ^ (r & 7)) << 4));        \
        }                                                                    \
    } while (0)

        E_LOAD_FRAGS(0, 0);
#pragma unroll
        for (int s = 0; s < 4; s++) {
            if (s < 3) E_LOAD_FRAGS((s + 1) & 1, s + 1);
#pragma unroll
            for (int mt = 0; mt < 2; mt++)
#pragma unroll
                for (int nt = 0; nt < 8; nt++)
                    mma16816(acc[mt][nt], af[s & 1][mt],
                             &bf_[s & 1][nt >> 1][(nt & 1) * 2]);
        }
#undef E_LOAD_FRAGS

        const int colbase = (ng * NTPC + it) * 128;
#pragma unroll
        for (int mt = 0; mt < 2; mt++)
#pragma unroll
            for (int nt = 0; nt < 8; nt++) {
                int col = colbase + wn * 64 + nt * 8 + cc;
#pragma unroll
                for (int h = 0; h < 2; h++) {
                    int row = m0 + wm * 32 + mt * 16 + cr + h * 8;
                    float e0 = __expf(acc[mt][nt][h * 2]);
                    float e1 = __expf(acc[mt][nt][h * 2 + 1]);
                    *(unsigned short*)(P + (size_t)row * Ll + col) =
                        f2_fp8x2(e0 * PSCALE, e1 * PSCALE);
                    rs[mt][h] += e0 + e1;
                }
            }
    }

#pragma unroll
    for (int mt = 0; mt < 2; mt++)
#pragma unroll
        for (int h = 0; h < 2; h++) {
            float v = rs[mt][h];
            v += __shfl_xor_sync(0xffffffffu, v, 1);
            v += __shfl_xor_sync(0xffffffffu, v, 2);
            rs[mt][h] = v;
        }
    __syncthreads();
    if ((lane & 3) == 0) {
#pragma unroll
        for (int mt = 0; mt < 2; mt++)
#pragma unroll
            for (int h = 0; h < 2; h++)
                s_part[wn * 128 + wm * 32 + mt * 16 + cr + h * 8] = rs[mt][h];
    }
    __syncthreads();
    if (t < 128) {
        size_t idx = ((size_t)bz * 8 + ng) * Ll + m0 + t;
        spart[idx] = s_part[t] + s_part[128 + t];
    }
}

// ---------------------------------------------------------------------------
// FP8 GEMM (out), per batch-chunk: pointers pre-offset, grid z = chunk size.
// ---------------------------------------------------------------------------
__global__ __launch_bounds__(256, 2) void fgemm(
    const unsigned char* __restrict__ Aall,
    const unsigned char* __restrict__ Ball,
    float* __restrict__ Cout,
    int K, int ldC,
    long long sA, long long sB, long long sC,
    const float* __restrict__ gptr,
    const float* __restrict__ Xall, long long sX,
    const float* __restrict__ invS)
{
    extern __shared__ __align__(1024) char sm[];
    const uint32_t smA = smem_u32(sm);
    const uint32_t smB = smA + 16384;

    const int t = threadIdx.x, lane = t & 31, wid = t >> 5;
    const int bz = blockIdx.z;
    const int m0 = blockIdx.y * 128, n0 = blockIdx.x * 128;
    const int wm = wid & 3, wn = wid >> 2;

    const unsigned char* A = Aall + (size_t)bz * sA + (size_t)m0 * K;
    const unsigned char* B = Ball + (size_t)bz * sB + (size_t)n0 * K;

    const int lrow = t >> 1;
    const int lc0  = (t & 1) * 4;
    const int lswz = lrow & 7;
    const unsigned char* Ar = A + (size_t)lrow * K;
    const unsigned char* Br = B + (size_t)lrow * K;
    const uint32_t dA0 = smA + lrow * 128;
    const uint32_t dB0 = smB + lrow * 128;

    float acc[2][8][4];
#pragma unroll
    for (int i = 0; i < 2; i++)
#pragma unroll
        for (int j = 0; j < 8; j++)
#pragma unroll
            for (int q = 0; q < 4; q++) acc[i][j][q] = 0.f;

#define LOAD_TILE8(stg, k0)                                                  \
    do {                                                                     \
        _Pragma("unroll")                                                    \
        for (int j = 0; j < 4; j++) {                                        \
            int c = lc0 + j;                                                 \
            uint32_t ph = (uint32_t)((c ^ lswz) << 4);                       \
            cp16u(dA0 + (stg) * STAGE_BYTES + ph, Ar + (k0) + c * 16);       \
            cp16u(dB0 + (stg) * STAGE_BYTES + ph, Br + (k0) + c * 16);       \
        }                                                                    \
        asm volatile("cp.async.commit_group;");                              \
    } while (0)

    const int nk = K / 128;
    LOAD_TILE8(0, 0);
    if (nk > 1) LOAD_TILE8(1, 128);

    const int a_r = lane & 15;
    const int a_ch = lane >> 4;
    const int b_r = ((lane >> 4) << 3) + (lane & 7);
    const int b_ch = (lane >> 3) & 1;

    int buf = 0;
    for (int kt = 0; kt < nk; kt++) {
        if (kt + 1 < nk) asm volatile("cp.async.wait_group 1;");
        else             asm volatile("cp.async.wait_group 0;");
        __syncthreads();

        if (kt + 2 < nk) {
            const int slot = (buf + 2 >= 3) ? buf - 1 : buf + 2;
            LOAD_TILE8(slot, (kt + 2) * 128);
        }

        const uint32_t bA = smA + buf * STAGE_BYTES;
        const uint32_t bB = smB + buf * STAGE_BYTES;

        uint32_t af[2][2][4];
        uint32_t bf_[2][4][4];

#define LOAD_FRAGS8(pp, s)                                                   \
    do {                                                                     \
        _Pragma("unroll")                                                    \
        for (int mt = 0; mt < 2; mt++) {                                     \
            int r = wm * 32 + mt * 16 + a_r;                                 \
            int c = (s) * 2 + a_ch;                                          \
            ldsm_x4(af[pp][mt], bA + r * 128 + ((c ^ (r & 7)) << 4));        \
        }                                                                    \
        _Pragma("unroll")                                                    \
        for (int ng = 0; ng < 4; ng++) {                                     \
            int r = wn * 64 + ng * 16 + b_r;                                 \
            int c = (s) * 2 + b_ch;                                          \
            ldsm_x4(bf_[pp][ng], bB + r * 128 + ((c ^ (r & 7)) << 4));       \
        }                                                                    \
    } while (0)

        LOAD_FRAGS8(0, 0);
#pragma unroll
        for (int s = 0; s < 4; s++) {
            if (s < 3) LOAD_FRAGS8((s + 1) & 1, s + 1);
#pragma unroll
            for (int mt = 0; mt < 2; mt++)
#pragma unroll
                for (int nt = 0; nt < 8; nt++)
                    mma16832f8(acc[mt][nt], af[s & 1][mt],
                               bf_[s & 1][nt >> 1][(nt & 1) * 2],
                               bf_[s & 1][nt >> 1][(nt & 1) * 2 + 1]);
        }
#undef LOAD_FRAGS8
        buf = (buf + 1 == 3) ? 0 : buf + 1;
    }
#undef LOAD_TILE8

    const int cr = lane >> 2;
    const int cc = (lane & 3) * 2;
    const float g = gptr[0] * 64.0f;
    const float* X = Xall + (size_t)bz * sX;
    const float* iS = invS + (size_t)bz * Ll;
    float* C = Cout + (size_t)bz * sC;
#pragma unroll
    for (int nt = 0; nt < 8; nt++) {
        int col = n0 + wn * 64 + nt * 8 + cc;
        float gi0 = g * iS[col];
        float gi1 = g * iS[col + 1];
#pragma unroll
        for (int mt = 0; mt < 2; mt++)
#pragma unroll
            for (int h = 0; h < 2; h++) {
                int row = m0 + wm * 32 + mt * 16 + cr + h * 8;
                float2 xv = *(const float2*)(X + (size_t)row * ldC + col);
                float2 o;
                o.x = fmaf(gi0, acc[mt][nt][h * 2], xv.x);
                o.y = fmaf(gi1, acc[mt][nt][h * 2 + 1], xv.y);
                *(float2*)(C + (size_t)row * ldC + col) = o;
            }
    }
}

// ---------------------------------------------------------------------------
__global__ __launch_bounds__(256) void reduce_s_kernel(
    const float* __restrict__ spart, float* __restrict__ invs)
{
    int idx = blockIdx.x * 256 + threadIdx.x;
    int b = idx >> 12, m = idx & 4095;
    float s = 0.f;
#pragma unroll
    for (int nt = 0; nt < 8; nt++)
        s += spart[((size_t)b * 8 + nt) * Ll + m];
    invs[idx] = 1.0f / s;
}

// ---------------------------------------------------------------------------
__global__ __launch_bounds__(256) void transpose_x_kernel(const float* __restrict__ x)
{
    __shared__ float tile[32][33];
    const int b  = blockIdx.z;
    const int c0 = blockIdx.y * 32;
    const int l0 = blockIdx.x * 32;
    const int tx = threadIdx.x, ty = threadIdx.y;

    const float* xb = x + ((size_t)b * Cc + c0) * Ll + l0;
#pragma unroll
    for (int r = 0; r < 4; r++)
        tile[ty + r * 8][tx] = xb[(size_t)(ty + r * 8) * Ll + tx];
    __syncthreads();

    __nv_bfloat16* o = g_xT + (size_t)b * Ll * Cc;
#pragma unroll
    for (int r = 0; r < 4; r++) {
        int l = l0 + ty + r * 8;
        o[(size_t)l * Cc + c0 + tx] = __float2bfloat16(tile[tx][ty + r * 8]);
    }
}

__global__ __launch_bounds__(256) void conv_wv_kernel(const float* __restrict__ Wv)
{
    int idx = blockIdx.x * 256 + threadIdx.x;
    g_wv[idx] = __float2bfloat16(Wv[idx]);
}

__global__ __launch_bounds__(256) void conv_wqk_kernel(
    const float* __restrict__ Wq, const float* __restrict__ Wk,
    const float* __restrict__ bq, const float* __restrict__ bk)
{
    int idx = blockIdx.x * 256 + threadIdx.x;
    int r = idx >> 9, c = idx & 511;
    float v = (r < 64) ? Wq[r * Cc + c] : Wk[(r - 64) * Cc + c];
    g_wqk[idx] = __float2bfloat16(v);
    if (idx < 128) g_bqk[idx] = (idx < 64) ? bq[idx] : bk[idx - 64];
}

// ---------------------------------------------------------------------------
extern "C" void kernel_launch(void* const* d_in, const int* in_sizes, int n_in,
                              void* d_out, int out_size)
{
    const float* x     = (const float*)d_in[0];
    const float* Wq    = (const float*)d_in[1];
    const float* bq    = (const float*)d_in[2];
    const float* Wk    = (const float*)d_in[3];
    const float* bk    = (const float*)d_in[4];
    const float* Wv    = (const float*)d_in[5];
    const float* bv    = (const float*)d_in[6];
    const float* gamma = (const float*)d_in[7];
    float* out = (float*)d_out;

    __nv_bfloat16 *qa, *kb, *xT, *wv, *wqk;
    unsigned char *v, *p;
    float *spart, *invs, *bqk;
    cudaGetSymbolAddress((void**)&qa, g_qa);
    cudaGetSymbolAddress((void**)&kb, g_kb);
    cudaGetSymbolAddress((void**)&xT, g_xT);
    cudaGetSymbolAddress((void**)&wv, g_wv);
    cudaGetSymbolAddress((void**)&wqk, g_wqk);
    cudaGetSymbolAddress((void**)&bqk, g_bqk);
    cudaGetSymbolAddress((void**)&v,  g_v);
    cudaGetSymbolAddress((void**)&p,  g_p);
    cudaGetSymbolAddress((void**)&spart, g_spart);
    cudaGetSymbolAddress((void**)&invs,  g_invs);

    cudaFuncSetAttribute(hgemm<1>, cudaFuncAttributeMaxDynamicSharedMemorySize, SMEM_SZ);
    cudaFuncSetAttribute(hgemm<4>, cudaFuncAttributeMaxDynamicSharedMemorySize, SMEM_SZ);
    cudaFuncSetAttribute(egemm,    cudaFuncAttributeMaxDynamicSharedMemorySize, ESMEM_SZ);
    cudaFuncSetAttribute(fgemm,    cudaFuncAttributeMaxDynamicSharedMemorySize, SMEM_SZ);

    static cudaStream_t s2 = nullptr;
    static cudaEvent_t evFork = nullptr, evW = nullptr, evT = nullptr;
    static cudaEvent_t evV = nullptr, evProj = nullptr, evE2 = nullptr;
    if (s2 == nullptr) {
        cudaStreamCreateWithFlags(&s2, cudaStreamNonBlocking);
        cudaEventCreateWithFlags(&evFork, cudaEventDisableTiming);
        cudaEventCreateWithFlags(&evW,    cudaEventDisableTiming);
        cudaEventCreateWithFlags(&evT,    cudaEventDisableTiming);
        cudaEventCreateWithFlags(&evV,    cudaEventDisableTiming);
        cudaEventCreateWithFlags(&evProj, cudaEventDisableTiming);
        cudaEventCreateWithFlags(&evE2,   cudaEventDisableTiming);
    }

    const int HB = Bb / 2;                 // 4 batches per chunk
    const long long sP  = (long long)Ll * Ll;
    const long long sQK = (long long)Ll * Dd;
    const long long sV  = (long long)Cc * Ll;

    // fork: side converts weights while main transposes x
    cudaEventRecord(evFork, 0);
    cudaStreamWaitEvent(s2, evFork, 0);

    conv_wqk_kernel<<<(128 * Cc) / 256, 256, 0, s2>>>(Wq, Wk, bq, bk);
    cudaEventRecord(evW, s2);
    conv_wv_kernel<<<(Cc * Cc) / 256, 256, 0, s2>>>(Wv);

    transpose_x_kernel<<<dim3(Ll / 32, Cc / 32, Bb), dim3(32, 8)>>>(x);
    cudaEventRecord(evT, 0);

    // side: v-proj (needs xT + wv)
    cudaStreamWaitEvent(s2, evT, 0);
    hgemm<1><<<dim3(Ll / 128, Cc / 128, Bb), 256, SMEM_SZ, s2>>>(
        wv, xT, v, nullptr, Cc, Ll,
        0LL, (long long)Ll * Cc, sV, bv);
    cudaEventRecord(evV, s2);

    // main: q/k projection (needs xT + wqk)
    cudaStreamWaitEvent(0, evW, 0);
    hgemm<4><<<dim3(1, Ll / 128, Bb), 256, SMEM_SZ>>>(
        xT, wqk, (unsigned char*)qa, kb, Cc, Dd,
        (long long)Ll * Cc, 0LL, 0LL, bqk);
    cudaEventRecord(evProj, 0);

    // main: energy + reduce for chunk 1 (b0-3)
    egemm<<<dim3(8, Ll / 128, HB), 256, ESMEM_SZ>>>(qa, kb, p, spart);
    reduce_s_kernel<<<(HB * Ll) / 256, 256>>>(spart, invs);

    // side: energy + reduce for chunk 2 (b4-7), overlaps fgemm chunk 1
    cudaStreamWaitEvent(s2, evProj, 0);
    egemm<<<dim3(8, Ll / 128, HB), 256, ESMEM_SZ, s2>>>(
        qa + (size_t)HB * sQK, kb + (size_t)HB * sQK,
        p + (size_t)HB * sP, spart + (size_t)HB * 8 * Ll);
    reduce_s_kernel<<<(HB * Ll) / 256, 256, 0, s2>>>(
        spart + (size_t)HB * 8 * Ll, invs + (size_t)HB * Ll);
    cudaEventRecord(evE2, s2);

    // main: fgemm chunk 1 (needs v + chunk-1 p/invS)
    cudaStreamWaitEvent(0, evV, 0);
    fgemm<<<dim3(Ll / 128, Cc / 128, HB), 256, SMEM_SZ>>>(
        v, p, out, Ll, Ll,
        sV, sP, sV, gamma, x, sV, invs);

    // main: fgemm chunk 2
    cudaStreamWaitEvent(0, evE2, 0);
    fgemm<<<dim3(Ll / 128, Cc / 128, HB), 256, SMEM_SZ>>>(
        v + (size_t)HB * sV, p + (size_t)HB * sP,
        out + (size_t)HB * sV, Ll, Ll,
        sV, sP, sV, gamma, x + (size_t)HB * sV, sV, invs + (size_t)HB * Ll);
}

// round 14
// speedup vs baseline: 1.1596x; 1.1596x over previous
#include <cuda_runtime.h>
#include <cuda_bf16.h>
#include <cuda_fp8.h>
#include <cstdint>

#define Bb 8
#define Cc 512
#define Ll 4096
#define Dd 64

#define PSCALE (1.0f / 64.0f)

// ---------------------------------------------------------------------------
// Scratch (device globals)
// ---------------------------------------------------------------------------
__device__ __nv_bfloat16 g_qa[(size_t)Bb * Ll * Dd];    // [B,L,64] q bf16
__device__ __nv_bfloat16 g_kb[(size_t)Bb * Ll * Dd];    // [B,L,64] k bf16
__device__ __nv_bfloat16 g_xT[(size_t)Bb * Ll * Cc];    // [B,L,C] bf16
__device__ __nv_bfloat16 g_wv[(size_t)Cc * Cc];         // [C,C] bf16
__device__ __nv_bfloat16 g_wqk[128 * Cc];               // [128,C] = [Wq;Wk] bf16
__device__ float         g_bqk[128];                    // [bq|bk]
__device__ unsigned char g_v [(size_t)Bb * Cc * Ll];    // [B,C,L] e4m3
__device__ unsigned char g_p [(size_t)Bb * Ll * Ll];    // [B,L,L] e4m3 exp(e)*2^-6
__device__ float g_spart[(size_t)Bb * 8 * Ll];          // [B,ngroup,L] partials

// ---------------------------------------------------------------------------
// helpers
// ---------------------------------------------------------------------------
__device__ __forceinline__ uint32_t smem_u32(const void* p) {
    uint32_t a;
    asm("{ .reg .u64 t; cvta.to.shared.u64 t, %1; cvt.u32.u64 %0, t; }"
        : "=r"(a) : "l"(p));
    return a;
}
__device__ __forceinline__ void cp16u(uint32_t s, const void* g) {
    asm volatile("cp.async.cg.shared.global [%0], [%1], 16;" :: "r"(s), "l"(g));
}
__device__ __forceinline__ void ldsm_x4(uint32_t* r, uint32_t addr) {
    asm volatile("ldmatrix.sync.aligned.m8n8.x4.shared.b16 {%0,%1,%2,%3}, [%4];"
                 : "=r"(r[0]), "=r"(r[1]), "=r"(r[2]), "=r"(r[3]) : "r"(addr));
}
__device__ __forceinline__ void mma16816(float* d, const uint32_t* a, const uint32_t* b) {
    asm volatile(
        "mma.sync.aligned.m16n8k16.row.col.f32.bf16.bf16.f32 "
        "{%0,%1,%2,%3}, {%4,%5,%6,%7}, {%8,%9}, {%0,%1,%2,%3};"
        : "+f"(d[0]), "+f"(d[1]), "+f"(d[2]), "+f"(d[3])
        : "r"(a[0]), "r"(a[1]), "r"(a[2]), "r"(a[3]), "r"(b[0]), "r"(b[1]));
}
__device__ __forceinline__ void mma16832f8(float* d, const uint32_t* a,
                                           uint32_t b0, uint32_t b1) {
    asm volatile(
        "mma.sync.aligned.m16n8k32.row.col.f32.e4m3.e4m3.f32 "
        "{%0,%1,%2,%3}, {%4,%5,%6,%7}, {%8,%9}, {%0,%1,%2,%3};"
        : "+f"(d[0]), "+f"(d[1]), "+f"(d[2]), "+f"(d[3])
        : "r"(a[0]), "r"(a[1]), "r"(a[2]), "r"(a[3]), "r"(b0), "r"(b1));
}
__device__ __forceinline__ unsigned short f2_fp8x2(float a, float b) {
    float2 f; f.x = a; f.y = b;
    return (unsigned short)__nv_cvt_float2_to_fp8x2(f, __NV_SATFINITE, __NV_E4M3);
}

static constexpr int STAGE_BYTES = 32768;
static constexpr int SMEM_SZ = 3 * STAGE_BYTES + 1024;
static constexpr int ESMEM_SZ = 4 * 16384 + 1024;

// ---------------------------------------------------------------------------
// bf16 HMMA GEMM: CTA 128x128, 256 thr (4m x 2n), k-tile 64, 3-stage.
// EPI 1: +bias[m], store e4m3
// EPI 4: +bias[n] stacked, split cols -> q / k bf16
// ---------------------------------------------------------------------------
template <int EPI>
__global__ __launch_bounds__(256, 2) void hgemm(
    const __nv_bfloat16* __restrict__ Aall,
    const __nv_bfloat16* __restrict__ Ball,
    unsigned char* __restrict__ Cout,
    void* __restrict__ Cout2,
    int K, int ldC,
    long long sA, long long sB, long long sC,
    const float* __restrict__ bias)
{
    extern __shared__ __align__(1024) char sm[];
    const uint32_t smA = smem_u32(sm);
    const uint32_t smB = smA + 16384;

    const int t = threadIdx.x, lane = t & 31, wid = t >> 5;
    const int bz = blockIdx.z;
    const int m0 = blockIdx.y * 128, n0 = blockIdx.x * 128;
    const int wm = wid & 3, wn = wid >> 2;

    const __nv_bfloat16* A = Aall + (size_t)bz * sA + (size_t)m0 * K;
    const __nv_bfloat16* B = Ball + (size_t)bz * sB + (size_t)n0 * K;

    const int lrow = t >> 1;
    const int lc0  = (t & 1) * 4;
    const int lswz = lrow & 7;
    const __nv_bfloat16* Ar = A + (size_t)lrow * K;
    const __nv_bfloat16* Br = B + (size_t)lrow * K;
    const uint32_t dA0 = smA + lrow * 128;
    const uint32_t dB0 = smB + lrow * 128;

    float acc[2][8][4];
#pragma unroll
    for (int i = 0; i < 2; i++)
#pragma unroll
        for (int j = 0; j < 8; j++)
#pragma unroll
            for (int q = 0; q < 4; q++) acc[i][j][q] = 0.f;

#define LOAD_TILE(stg, k0)                                                   \
    do {                                                                     \
        _Pragma("unroll")                                                    \
        for (int j = 0; j < 4; j++) {                                        \
            int c = lc0 + j;                                                 \
            uint32_t ph = (uint32_t)((c ^ lswz) << 4);                       \
            cp16u(dA0 + (stg) * STAGE_BYTES + ph, Ar + (k0) + c * 8);        \
            cp16u(dB0 + (stg) * STAGE_BYTES + ph, Br + (k0) + c * 8);        \
        }                                                                    \
        asm volatile("cp.async.commit_group;");                              \
    } while (0)

    const int nk = K / 64;
    LOAD_TILE(0, 0);
    if (nk > 1) LOAD_TILE(1, 64);

    const int a_r = lane & 15;
    const int a_ch = lane >> 4;
    const int b_r = ((lane >> 4) << 3) + (lane & 7);
    const int b_ch = (lane >> 3) & 1;

    int buf = 0;
    for (int kt = 0; kt < nk; kt++) {
        if (kt + 1 < nk) asm volatile("cp.async.wait_group 1;");
        else             asm volatile("cp.async.wait_group 0;");
        __syncthreads();

        if (kt + 2 < nk) {
            const int slot = (buf + 2 >= 3) ? buf - 1 : buf + 2;
            LOAD_TILE(slot, (kt + 2) * 64);
        }

        const uint32_t bA = smA + buf * STAGE_BYTES;
        const uint32_t bB = smB + buf * STAGE_BYTES;

        uint32_t af[2][2][4];
        uint32_t bf_[2][4][4];

#define LOAD_FRAGS(pp, s)                                                    \
    do {                                                                     \
        _Pragma("unroll")                                                    \
        for (int mt = 0; mt < 2; mt++) {                                     \
            int r = wm * 32 + mt * 16 + a_r;                                 \
            int c = (s) * 2 + a_ch;                                          \
            ldsm_x4(af[pp][mt], bA + r * 128 + ((c ^ (r & 7)) << 4));        \
        }                                                                    \
        _Pragma("unroll")                                                    \
        for (int ng = 0; ng < 4; ng++) {                                     \
            int r = wn * 64 + ng * 16 + b_r;                                 \
            int c = (s) * 2 + b_ch;                                          \
            ldsm_x4(bf_[pp][ng], bB + r * 128 + ((c ^ (r & 7)) << 4));       \
        }                                                                    \
    } while (0)

        LOAD_FRAGS(0, 0);
#pragma unroll
        for (int s = 0; s < 4; s++) {
            if (s < 3) LOAD_FRAGS((s + 1) & 1, s + 1);
#pragma unroll
            for (int mt = 0; mt < 2; mt++)
#pragma unroll
                for (int nt = 0; nt < 8; nt++)
                    mma16816(acc[mt][nt], af[s & 1][mt],
                             &bf_[s & 1][nt >> 1][(nt & 1) * 2]);
        }
#undef LOAD_FRAGS
        buf = (buf + 1 == 3) ? 0 : buf + 1;
    }
#undef LOAD_TILE

    const int cr = lane >> 2;
    const int cc = (lane & 3) * 2;

    if (EPI == 1) {
        unsigned char* C = Cout + (size_t)bz * sC;
#pragma unroll
        for (int mt = 0; mt < 2; mt++) {
            float bv0 = bias[m0 + wm * 32 + mt * 16 + cr];
            float bv1 = bias[m0 + wm * 32 + mt * 16 + cr + 8];
#pragma unroll
            for (int nt = 0; nt < 8; nt++) {
                int col = n0 + wn * 64 + nt * 8 + cc;
#pragma unroll
                for (int h = 0; h < 2; h++) {
                    int row = m0 + wm * 32 + mt * 16 + cr + h * 8;
                    float bv = h ? bv1 : bv0;
                    *(unsigned short*)(C + (size_t)row * ldC + col) =
                        f2_fp8x2(acc[mt][nt][h * 2] + bv, acc[mt][nt][h * 2 + 1] + bv);
                }
            }
        }
    } else {
        __nv_bfloat16* Q  = (__nv_bfloat16*)Cout  + (size_t)bz * Ll * Dd;
        __nv_bfloat16* Kk = (__nv_bfloat16*)Cout2 + (size_t)bz * Ll * Dd;
#pragma unroll
        for (int nt = 0; nt < 8; nt++) {
            int col = wn * 64 + nt * 8 + cc;
            float bv0 = bias[col];
            float bv1 = bias[col + 1];
            __nv_bfloat16* dst = (col < 64) ? Q : Kk;
            int dcol = col & 63;
#pragma unroll
            for (int mt = 0; mt < 2; mt++)
#pragma unroll
                for (int h = 0; h < 2; h++) {
                    int row = m0 + wm * 32 + mt * 16 + cr + h * 8;
                    __nv_bfloat162 o;
                    o.x = __float2bfloat16(acc[mt][nt][h * 2] + bv0);
                    o.y = __float2bfloat16(acc[mt][nt][h * 2 + 1] + bv1);
                    *(__nv_bfloat162*)(dst + (size_t)row * Dd + dcol) = o;
                }
        }
    }
}

// ---------------------------------------------------------------------------
// Energy GEMM: p = exp(q @ k^T)*2^-6, K=64. A resident; loops 4 n-tiles;
// rowsums -> spart [B,8,L]. grid (8, 32, B).
// ---------------------------------------------------------------------------
__global__ __launch_bounds__(256, 2) void egemm(
    const __nv_bfloat16* __restrict__ Qall,
    const __nv_bfloat16* __restrict__ Kall,
    unsigned char* __restrict__ Pout,
    float* __restrict__ spart)
{
    constexpr int NTPC = 4;
    extern __shared__ __align__(1024) char sm[];
    const uint32_t smA = smem_u32(sm);
    const uint32_t smB = smA + 16384;
    float* s_part = (float*)(sm + 4 * 16384);

    const int t = threadIdx.x, lane = t & 31, wid = t >> 5;
    const int bz = blockIdx.z;
    const int m0 = blockIdx.y * 128;
    const int ng = blockIdx.x;
    const int wm = wid & 3, wn = wid >> 2;

    const __nv_bfloat16* Q  = Qall + (size_t)bz * Ll * Dd + (size_t)m0 * Dd;
    const __nv_bfloat16* Kb = Kall + (size_t)bz * Ll * Dd
                              + (size_t)ng * NTPC * 128 * Dd;

    const int lrow = t >> 1;
    const int lc0  = (t & 1) * 4;
    const int lswz = lrow & 7;
    const __nv_bfloat16* Ar = Q  + (size_t)lrow * Dd;
    const __nv_bfloat16* Br = Kb + (size_t)lrow * Dd;
    const uint32_t dA = smA + lrow * 128;
    const uint32_t dB = smB + lrow * 128;

#pragma unroll
    for (int j = 0; j < 4; j++) {
        int c = lc0 + j;
        uint32_t ph = (uint32_t)((c ^ lswz) << 4);
        cp16u(dA + ph, Ar + c * 8);
        cp16u(dB + ph, Br + c * 8);
    }
    asm volatile("cp.async.commit_group;");
#pragma unroll
    for (int j = 0; j < 4; j++) {
        int c = lc0 + j;
        uint32_t ph = (uint32_t)((c ^ lswz) << 4);
        cp16u(dB + 16384 + ph, Br + 8192 + c * 8);
    }
    asm volatile("cp.async.commit_group;");

    const int a_r = lane & 15;
    const int a_ch = lane >> 4;
    const int b_r = ((lane >> 4) << 3) + (lane & 7);
    const int b_ch = (lane >> 3) & 1;
    const int cr = lane >> 2;
    const int cc = (lane & 3) * 2;

    float rs[2][2] = {{0.f, 0.f}, {0.f, 0.f}};
    unsigned char* P = Pout + (size_t)bz * Ll * Ll;

    for (int it = 0; it < NTPC; it++) {
        asm volatile("cp.async.wait_group 1;");
        __syncthreads();

        if (it + 2 < NTPC) {
            const int stg = (it + 2) % 3;
#pragma unroll
            for (int j = 0; j < 4; j++) {
                int c = lc0 + j;
                uint32_t ph = (uint32_t)((c ^ lswz) << 4);
                cp16u(dB + stg * 16384 + ph, Br + (size_t)(it + 2) * 8192 + c * 8);
            }
        }
        asm volatile("cp.async.commit_group;");

        const uint32_t bB = smB + (it % 3) * 16384;

        float acc[2][8][4];
#pragma unroll
        for (int i = 0; i < 2; i++)
#pragma unroll
            for (int j = 0; j < 8; j++)
#pragma unroll
                for (int q = 0; q < 4; q++) acc[i][j][q] = 0.f;

        uint32_t af[2][2][4];
        uint32_t bf_[2][4][4];

#define E_LOAD_FRAGS(pp, s)                                                  \
    do {                                                                     \
        _Pragma("unroll")                                                    \
        for (int mt = 0; mt < 2; mt++) {                                     \
            int r = wm * 32 + mt * 16 + a_r;                                 \
            int c = (s) * 2 + a_ch;                                          \
            ldsm_x4(af[pp][mt], smA + r * 128 + ((c ^ (r & 7)) << 4));       \
        }                                                                    \
        _Pragma("unroll")                                                    \
        for (int g = 0; g < 4; g++) {                                        \
            int r = wn * 64 + g * 16 + b_r;                                  \
            int c = (s) * 2 + b_ch;                                          \
            ldsm_x4(bf_[pp][g], bB + r * 128 + ((c ^ (r & 7)) << 4));        \
        }                                                                    \
    } while (0)

        E_LOAD_FRAGS(0, 0);
#pragma unroll
        for (int s = 0; s < 4; s++) {
            if (s < 3) E_LOAD_FRAGS((s + 1) & 1, s + 1);
#pragma unroll
            for (int mt = 0; mt < 2; mt++)
#pragma unroll
                for (int nt = 0; nt < 8; nt++)
                    mma16816(acc[mt][nt], af[s & 1][mt],
                             &bf_[s & 1][nt >> 1][(nt & 1) * 2]);
        }
#undef E_LOAD_FRAGS

        const int colbase = (ng * NTPC + it) * 128;
#pragma unroll
        for (int mt = 0; mt < 2; mt++)
#pragma unroll
            for (int nt = 0; nt < 8; nt++) {
                int col = colbase + wn * 64 + nt * 8 + cc;
#pragma unroll
                for (int h = 0; h < 2; h++) {
                    int row = m0 + wm * 32 + mt * 16 + cr + h * 8;
                    float e0 = __expf(acc[mt][nt][h * 2]);
                    float e1 = __expf(acc[mt][nt][h * 2 + 1]);
                    *(unsigned short*)(P + (size_t)row * Ll + col) =
                        f2_fp8x2(e0 * PSCALE, e1 * PSCALE);
                    rs[mt][h] += e0 + e1;
                }
            }
    }

#pragma unroll
    for (int mt = 0; mt < 2; mt++)
#pragma unroll
        for (int h = 0; h < 2; h++) {
            float v = rs[mt][h];
            v += __shfl_xor_sync(0xffffffffu, v, 1);
            v += __shfl_xor_sync(0xffffffffu, v, 2);
            rs[mt][h] = v;
        }
    __syncthreads();
    if ((lane & 3) == 0) {
#pragma unroll
        for (int mt = 0; mt < 2; mt++)
#pragma unroll
            for (int h = 0; h < 2; h++)
                s_part[wn * 128 + wm * 32 + mt * 16 + cr + h * 8] = rs[mt][h];
    }
    __syncthreads();
    if (t < 128) {
        size_t idx = ((size_t)bz * 8 + ng) * Ll + m0 + t;
        spart[idx] = s_part[t] + s_part[128 + t];
    }
}

// ---------------------------------------------------------------------------
// FP8 GEMM (out): CTA 128x128, k-tile 128 bytes.
// Epilogue computes invS inline from spart (sum of 8 partials per column):
// C = (gamma*64/rowsum[n])*acc + X[m][n], fp32.
// ---------------------------------------------------------------------------
__global__ __launch_bounds__(256, 2) void fgemm(
    const unsigned char* __restrict__ Aall,
    const unsigned char* __restrict__ Ball,
    float* __restrict__ Cout,
    int K, int ldC,
    long long sA, long long sB, long long sC,
    const float* __restrict__ gptr,
    const float* __restrict__ Xall, long long sX,
    const float* __restrict__ spart)
{
    extern __shared__ __align__(1024) char sm[];
    const uint32_t smA = smem_u32(sm);
    const uint32_t smB = smA + 16384;

    const int t = threadIdx.x, lane = t & 31, wid = t >> 5;
    const int bz = blockIdx.z;
    const int m0 = blockIdx.y * 128, n0 = blockIdx.x * 128;
    const int wm = wid & 3, wn = wid >> 2;

    const unsigned char* A = Aall + (size_t)bz * sA + (size_t)m0 * K;
    const unsigned char* B = Ball + (size_t)bz * sB + (size_t)n0 * K;

    const int lrow = t >> 1;
    const int lc0  = (t & 1) * 4;
    const int lswz = lrow & 7;
    const unsigned char* Ar = A + (size_t)lrow * K;
    const unsigned char* Br = B + (size_t)lrow * K;
    const uint32_t dA0 = smA + lrow * 128;
    const uint32_t dB0 = smB + lrow * 128;

    float acc[2][8][4];
#pragma unroll
    for (int i = 0; i < 2; i++)
#pragma unroll
        for (int j = 0; j < 8; j++)
#pragma unroll
            for (int q = 0; q < 4; q++) acc[i][j][q] = 0.f;

#define LOAD_TILE8(stg, k0)                                                  \
    do {                                                                     \
        _Pragma("unroll")                                                    \
        for (int j = 0; j < 4; j++) {                                        \
            int c = lc0 + j;                                                 \
            uint32_t ph = (uint32_t)((c ^ lswz) << 4);                       \
            cp16u(dA0 + (stg) * STAGE_BYTES + ph, Ar + (k0) + c * 16);       \
            cp16u(dB0 + (stg) * STAGE_BYTES + ph, Br + (k0) + c * 16);       \
        }                                                                    \
        asm volatile("cp.async.commit_group;");                              \
    } while (0)

    const int nk = K / 128;
    LOAD_TILE8(0, 0);
    if (nk > 1) LOAD_TILE8(1, 128);

    const int a_r = lane & 15;
    const int a_ch = lane >> 4;
    const int b_r = ((lane >> 4) << 3) + (lane & 7);
    const int b_ch = (lane >> 3) & 1;

    int buf = 0;
    for (int kt = 0; kt < nk; kt++) {
        if (kt + 1 < nk) asm volatile("cp.async.wait_group 1;");
        else             asm volatile("cp.async.wait_group 0;");
        __syncthreads();

        if (kt + 2 < nk) {
            const int slot = (buf + 2 >= 3) ? buf - 1 : buf + 2;
            LOAD_TILE8(slot, (kt + 2) * 128);
        }

        const uint32_t bA = smA + buf * STAGE_BYTES;
        const uint32_t bB = smB + buf * STAGE_BYTES;

        uint32_t af[2][2][4];
        uint32_t bf_[2][4][4];

#define LOAD_FRAGS8(pp, s)                                                   \
    do {                                                                     \
        _Pragma("unroll")                                                    \
        for (int mt = 0; mt < 2; mt++) {                                     \
            int r = wm * 32 + mt * 16 + a_r;                                 \
            int c = (s) * 2 + a_ch;                                          \
            ldsm_x4(af[pp][mt], bA + r * 128 + ((c ^ (r & 7)) << 4));        \
        }                                                                    \
        _Pragma("unroll")                                                    \
        for (int ng = 0; ng < 4; ng++) {                                     \
            int r = wn * 64 + ng * 16 + b_r;                                 \
            int c = (s) * 2 + b_ch;                                          \
            ldsm_x4(bf_[pp][ng], bB + r * 128 + ((c ^ (r & 7)) << 4));       \
        }                                                                    \
    } while (0)

        LOAD_FRAGS8(0, 0);
#pragma unroll
        for (int s = 0; s < 4; s++) {
            if (s < 3) LOAD_FRAGS8((s + 1) & 1, s + 1);
#pragma unroll
            for (int mt = 0; mt < 2; mt++)
#pragma unroll
                for (int nt = 0; nt < 8; nt++)
                    mma16832f8(acc[mt][nt], af[s & 1][mt],
                               bf_[s & 1][nt >> 1][(nt & 1) * 2],
                               bf_[s & 1][nt >> 1][(nt & 1) * 2 + 1]);
        }
#undef LOAD_FRAGS8
        buf = (buf + 1 == 3) ? 0 : buf + 1;
    }
#undef LOAD_TILE8

    const int cr = lane >> 2;
    const int cc = (lane & 3) * 2;
    const float g = gptr[0] * 64.0f;
    const float* X = Xall + (size_t)bz * sX;
    const float* sp = spart + (size_t)bz * 8 * Ll;
    float* C = Cout + (size_t)bz * sC;
#pragma unroll
    for (int nt = 0; nt < 8; nt++) {
        int col = n0 + wn * 64 + nt * 8 + cc;
        float s0 = 0.f, s1 = 0.f;
#pragma unroll
        for (int j = 0; j < 8; j++) {
            s0 += sp[(size_t)j * Ll + col];
            s1 += sp[(size_t)j * Ll + col + 1];
        }
        float gi0 = g / s0;
        float gi1 = g / s1;
#pragma unroll
        for (int mt = 0; mt < 2; mt++)
#pragma unroll
            for (int h = 0; h < 2; h++) {
                int row = m0 + wm * 32 + mt * 16 + cr + h * 8;
                float2 xv = *(const float2*)(X + (size_t)row * ldC + col);
                float2 o;
                o.x = fmaf(gi0, acc[mt][nt][h * 2], xv.x);
                o.y = fmaf(gi1, acc[mt][nt][h * 2 + 1], xv.y);
                *(float2*)(C + (size_t)row * ldC + col) = o;
            }
    }
}

// ---------------------------------------------------------------------------
__global__ __launch_bounds__(256) void transpose_x_kernel(const float* __restrict__ x)
{
    __shared__ float tile[32][33];
    const int b  = blockIdx.z;
    const int c0 = blockIdx.y * 32;
    const int l0 = blockIdx.x * 32;
    const int tx = threadIdx.x, ty = threadIdx.y;

    const float* xb = x + ((size_t)b * Cc + c0) * Ll + l0;
#pragma unroll
    for (int r = 0; r < 4; r++)
        tile[ty + r * 8][tx] = xb[(size_t)(ty + r * 8) * Ll + tx];
    __syncthreads();

    __nv_bfloat16* o = g_xT + (size_t)b * Ll * Cc;
#pragma unroll
    for (int r = 0; r < 4; r++) {
        int l = l0 + ty + r * 8;
        o[(size_t)l * Cc + c0 + tx] = __float2bfloat16(tile[tx][ty + r * 8]);
    }
}

__global__ __launch_bounds__(256) void conv_wv_kernel(const float* __restrict__ Wv)
{
    int idx = blockIdx.x * 256 + threadIdx.x;
    g_wv[idx] = __float2bfloat16(Wv[idx]);
}

__global__ __launch_bounds__(256) void conv_wqk_kernel(
    const float* __restrict__ Wq, const float* __restrict__ Wk,
    const float* __restrict__ bq, const float* __restrict__ bk)
{
    int idx = blockIdx.x * 256 + threadIdx.x;
    int r = idx >> 9, c = idx & 511;
    float v = (r < 64) ? Wq[r * Cc + c] : Wk[(r - 64) * Cc + c];
    g_wqk[idx] = __float2bfloat16(v);
    if (idx < 128) g_bqk[idx] = (idx < 64) ? bq[idx] : bk[idx - 64];
}

// ---------------------------------------------------------------------------
extern "C" void kernel_launch(void* const* d_in, const int* in_sizes, int n_in,
                              void* d_out, int out_size)
{
    const float* x     = (const float*)d_in[0];
    const float* Wq    = (const float*)d_in[1];
    const float* bq    = (const float*)d_in[2];
    const float* Wk    = (const float*)d_in[3];
    const float* bk    = (const float*)d_in[4];
    const float* Wv    = (const float*)d_in[5];
    const float* bv    = (const float*)d_in[6];
    const float* gamma = (const float*)d_in[7];
    float* out = (float*)d_out;

    __nv_bfloat16 *qa, *kb, *xT, *wv, *wqk;
    unsigned char *v, *p;
    float *spart, *bqk;
    cudaGetSymbolAddress((void**)&qa, g_qa);
    cudaGetSymbolAddress((void**)&kb, g_kb);
    cudaGetSymbolAddress((void**)&xT, g_xT);
    cudaGetSymbolAddress((void**)&wv, g_wv);
    cudaGetSymbolAddress((void**)&wqk, g_wqk);
    cudaGetSymbolAddress((void**)&bqk, g_bqk);
    cudaGetSymbolAddress((void**)&v,  g_v);
    cudaGetSymbolAddress((void**)&p,  g_p);
    cudaGetSymbolAddress((void**)&spart, g_spart);

    cudaFuncSetAttribute(hgemm<1>, cudaFuncAttributeMaxDynamicSharedMemorySize, SMEM_SZ);
    cudaFuncSetAttribute(hgemm<4>, cudaFuncAttributeMaxDynamicSharedMemorySize, SMEM_SZ);
    cudaFuncSetAttribute(egemm,    cudaFuncAttributeMaxDynamicSharedMemorySize, ESMEM_SZ);
    cudaFuncSetAttribute(fgemm,    cudaFuncAttributeMaxDynamicSharedMemorySize, SMEM_SZ);

    static cudaStream_t s2 = nullptr;
    static cudaEvent_t evFork = nullptr, evW = nullptr, evT = nullptr, evJoin = nullptr;
    if (s2 == nullptr) {
        cudaStreamCreateWithFlags(&s2, cudaStreamNonBlocking);
        cudaEventCreateWithFlags(&evFork, cudaEventDisableTiming);
        cudaEventCreateWithFlags(&evW,    cudaEventDisableTiming);
        cudaEventCreateWithFlags(&evT,    cudaEventDisableTiming);
        cudaEventCreateWithFlags(&evJoin, cudaEventDisableTiming);
    }

    // fork: side converts weights while main transposes x
    cudaEventRecord(evFork, 0);
    cudaStreamWaitEvent(s2, evFork, 0);

    conv_wqk_kernel<<<(128 * Cc) / 256, 256, 0, s2>>>(Wq, Wk, bq, bk);
    cudaEventRecord(evW, s2);
    conv_wv_kernel<<<(Cc * Cc) / 256, 256, 0, s2>>>(Wv);

    transpose_x_kernel<<<dim3(Ll / 32, Cc / 32, Bb), dim3(32, 8)>>>(x);
    cudaEventRecord(evT, 0);

    // side: v-proj (needs xT + wv)
    cudaStreamWaitEvent(s2, evT, 0);
    hgemm<1><<<dim3(Ll / 128, Cc / 128, Bb), 256, SMEM_SZ, s2>>>(
        wv, xT, v, nullptr, Cc, Ll,
        0LL, (long long)Ll * Cc, (long long)Cc * Ll, bv);
    cudaEventRecord(evJoin, s2);

    // main: q/k projection (needs xT + wqk)
    cudaStreamWaitEvent(0, evW, 0);
    hgemm<4><<<dim3(1, Ll / 128, Bb), 256, SMEM_SZ>>>(
        xT, wqk, (unsigned char*)qa, kb, Cc, Dd,
        (long long)Ll * Cc, 0LL, 0LL, bqk);

    // main: energy + exp -> p, partials
    egemm<<<dim3(8, Ll / 128, Bb), 256, ESMEM_SZ>>>(qa, kb, p, spart);

    // join: fgemm needs v (side) and p/spart (main); invS computed inline
    cudaStreamWaitEvent(0, evJoin, 0);
    fgemm<<<dim3(Ll / 128, Cc / 128, Bb), 256, SMEM_SZ>>>(
        v, p, out, Ll, Ll,
        (long long)Cc * Ll, (long long)Ll * Ll, (long long)Cc * Ll,
        gamma, x, (long long)Cc * Ll, spart);
}